// round 11
// baseline (speedup 1.0000x reference)
#include <cuda_runtime.h>
#include <cuda_bf16.h>

// Problem constants
#define BS1 32
#define BS2 128
#define NUM_EC 64
#define MEM_DIM 256
#define MLP_DIM 256
#define Q_DIM 256           // 4 * CONV_DIM

// Scratch (device globals — allocation is forbidden)
__device__ float g_att[BS1 * NUM_EC];              // softmax_e(criteria·Wa_c)
__device__ float g_PE [BS2 * MLP_DIM];             // ehr @ Wm_e

// ---- PDL primitives ----
__device__ __forceinline__ void pdl_trigger() {
    asm volatile("griddepcontrol.launch_dependents;");
}
__device__ __forceinline__ void pdl_wait() {
    asm volatile("griddepcontrol.wait;" ::: "memory");
}

// ---- packed f32x2 helpers ----
__device__ __forceinline__ unsigned long long pk2(float lo, float hi) {
    unsigned long long r;
    asm("mov.b64 %0, {%1, %2};" : "=l"(r)
        : "r"(__float_as_uint(lo)), "r"(__float_as_uint(hi)));
    return r;
}
__device__ __forceinline__ unsigned long long fma2(unsigned long long a,
                                                   unsigned long long b,
                                                   unsigned long long c) {
    unsigned long long d;
    asm("fma.rn.f32x2 %0, %1, %2, %3;" : "=l"(d) : "l"(a), "l"(b), "l"(c));
    return d;
}
__device__ __forceinline__ float2 upk2(unsigned long long v) {
    unsigned int lo, hi;
    asm("mov.b64 {%0, %1}, %2;" : "=r"(lo), "=r"(hi) : "l"(v));
    return make_float2(__uint_as_float(lo), __uint_as_float(hi));
}

// ---------------------------------------------------------------------------
// Pre kernel (tiny, 64 blocks; fully overlapped with k_main's GEMM phase):
//   bids [0,32):   att[b,:] = softmax_e(criteria[b,e,:]·Wa_c)
//                  (logit_e[p] and b_align are constant over e -> cancel)
//   bids [32,64):  PE[p,d] = dot(ehr[p,:], Wm_e[:,d])   (4 p / block)
// ---------------------------------------------------------------------------
#define ATT_BLOCKS  32
#define PE_BLOCKS   32
#define PE_P_TILE   4

__global__ void __launch_bounds__(256) k_pre(const float* __restrict__ ehr,
                                             const float* __restrict__ crit,
                                             const float* __restrict__ W_align,
                                             const float* __restrict__ W_mlp) {
    __shared__ float sbuf[PE_P_TILE * MEM_DIM];
    const int bid = blockIdx.x;
    const int tid = threadIdx.x;

    if (bid < ATT_BLOCKS) {
        // ----- att -----
        const int b = bid;
        const int e = tid >> 2;
        const int q = tid & 3;

        const float4* row = (const float4*)(crit + ((size_t)(b * NUM_EC + e)) * Q_DIM);
        const float4* wa  = (const float4*)W_align;

        float s = 0.f;
        #pragma unroll
        for (int i = 0; i < 16; ++i) {
            float4 c = row[q * 16 + i];
            float4 w = wa [q * 16 + i];
            s += c.x * w.x + c.y * w.y + c.z * w.z + c.w * w.w;
        }
        s += __shfl_xor_sync(0xffffffffu, s, 1);
        s += __shfl_xor_sync(0xffffffffu, s, 2);

        float* sm = sbuf;
        if (q == 0) sm[e] = s;
        __syncthreads();

        if (tid < 32) {
            float a  = sm[tid];
            float bb = sm[tid + 32];
            float m = fmaxf(a, bb);
            #pragma unroll
            for (int off = 16; off; off >>= 1)
                m = fmaxf(m, __shfl_xor_sync(0xffffffffu, m, off));
            float ea = expf(a - m);
            float eb = expf(bb - m);
            float ss = ea + eb;
            #pragma unroll
            for (int off = 16; off; off >>= 1)
                ss += __shfl_xor_sync(0xffffffffu, ss, off);
            float inv = 1.f / ss;
            g_att[b * NUM_EC + tid]      = ea * inv;
            g_att[b * NUM_EC + tid + 32] = eb * inv;
        }
        __syncthreads();
        pdl_trigger();

    } else {
        // ----- PE -----
        const int pg = bid - ATT_BLOCKS;
        const int p0 = pg * PE_P_TILE;
        const int d  = tid;

        float* es = sbuf;                  // [PE_P_TILE][MEM_DIM]
        #pragma unroll
        for (int i = 0; i < PE_P_TILE; ++i)
            es[i * MEM_DIM + d] = ehr[(size_t)(p0 + i) * MEM_DIM + d];
        __syncthreads();

        float acc[PE_P_TILE];
        #pragma unroll
        for (int i = 0; i < PE_P_TILE; ++i) acc[i] = 0.f;

        const float* w = W_mlp + (size_t)Q_DIM * MLP_DIM + d;
        #pragma unroll 4
        for (int k = 0; k < MEM_DIM; ++k) {
            float wv = w[(size_t)k * MLP_DIM];
            #pragma unroll
            for (int i = 0; i < PE_P_TILE; ++i)
                acc[i] += es[i * MEM_DIM + k] * wv;
        }
        #pragma unroll
        for (int i = 0; i < PE_P_TILE; ++i)
            g_PE[(size_t)(p0 + i) * MLP_DIM + d] = acc[i];
        pdl_trigger();
    }
}

// ---------------------------------------------------------------------------
// Main kernel: GEMM fused into the store kernel.
// grid = 32 b x 8 e-tiles = 256 blocks, 512 threads.
// Thread (e = tid>>6, dg = tid&63, d0 = dg*4):
//   Phase 1 (inputs only, overlaps k_pre via PDL):
//     pc[4] = dot(criteria[b,e0+e,:], Wm_c[:,d0..d0+3])  -- FMA2 over d pairs,
//     criteria in smem (broadcast LDS.128), W rows coalesced LDG.128.
//   pdl_wait()
//   Phase 2 (store): for p in 0..127:
//     out[b,p,e0+e,d0..3] = att[b,e0+e]*(pc + PE[p,d0..3]) + b_mlp[d0..3]
//     1 LDG.128 + 1 STG.128 per p per thread; __stcs streaming.
// PC never touches memory — it lives in 4 registers.
// ---------------------------------------------------------------------------
#define MAIN_BLOCKS (BS1 * 8)     // 256
__global__ void __launch_bounds__(512) k_main(float* __restrict__ out,
                                              const float* __restrict__ crit,
                                              const float* __restrict__ W_mlp,
                                              const float* __restrict__ b_mlp) {
    __shared__ __align__(16) float4 cs4[8 * 64];   // criteria[b, e0..e0+7, :], 8 KB
    const int bid = blockIdx.x;
    const int b   = bid >> 3;
    const int e0  = (bid & 7) * 8;
    const int tid = threadIdx.x;
    const int e   = tid >> 6;          // 0..7
    const int dg  = tid & 63;          // float4 lane in d
    const int d0  = dg * 4;

    // ---- Phase 1: load criteria tile, compute PC in registers ----
    const float4* src = (const float4*)(crit + (size_t)(b * NUM_EC + e0) * Q_DIM);
    cs4[tid] = src[tid];               // 512 float4, one per thread
    __syncthreads();

    unsigned long long a01 = 0ull, a23 = 0ull;
    const float4* crow = cs4 + e * 64;
    const float4* wrow = (const float4*)W_mlp + dg;    // row stride 64 float4

    #pragma unroll 4
    for (int j = 0; j < 64; ++j) {
        const float4 c  = crow[j];                     // broadcast LDS.128
        const float4 w0 = __ldg(wrow + (size_t)(4 * j + 0) * 64);
        const float4 w1 = __ldg(wrow + (size_t)(4 * j + 1) * 64);
        const float4 w2 = __ldg(wrow + (size_t)(4 * j + 2) * 64);
        const float4 w3 = __ldg(wrow + (size_t)(4 * j + 3) * 64);
        const unsigned long long cx = pk2(c.x, c.x);
        const unsigned long long cy = pk2(c.y, c.y);
        const unsigned long long cz = pk2(c.z, c.z);
        const unsigned long long cw = pk2(c.w, c.w);
        a01 = fma2(cx, pk2(w0.x, w0.y), a01);  a23 = fma2(cx, pk2(w0.z, w0.w), a23);
        a01 = fma2(cy, pk2(w1.x, w1.y), a01);  a23 = fma2(cy, pk2(w1.z, w1.w), a23);
        a01 = fma2(cz, pk2(w2.x, w2.y), a01);  a23 = fma2(cz, pk2(w2.z, w2.w), a23);
        a01 = fma2(cw, pk2(w3.x, w3.y), a01);  a23 = fma2(cw, pk2(w3.z, w3.w), a23);
    }
    const float2 lo = upk2(a01);
    const float2 hi = upk2(a23);
    const float4 pc = make_float4(lo.x, lo.y, hi.x, hi.y);

    // ---- Wait for k_pre's att/PE ----
    pdl_wait();

    const float  a  = __ldg(&g_att[b * NUM_EC + e0 + e]);
    const float4 bm = __ldg((const float4*)b_mlp + dg);
    const float4* pe4 = (const float4*)g_PE + dg;      // row stride 64 float4

    float4* o = (float4*)out;
    // float4 index: ((b*128 + p)*64 + (e0+e))*64 + dg
    const size_t base   = ((size_t)b * BS2 * NUM_EC + (size_t)(e0 + e)) * 64 + dg;
    const size_t pstep  = (size_t)NUM_EC * 64;         // 4096 float4 per p

    const float px = pc.x, py = pc.y, pz = pc.z, pw = pc.w;

    #pragma unroll 4
    for (int p = 0; p < BS2; ++p) {
        const float4 pe = __ldg(pe4 + (size_t)p * 64);
        float4 r;
        r.x = fmaf(a, px + pe.x, bm.x);
        r.y = fmaf(a, py + pe.y, bm.y);
        r.z = fmaf(a, pz + pe.z, bm.z);
        r.w = fmaf(a, pw + pe.w, bm.w);
        __stcs(&o[base + (size_t)p * pstep], r);
    }
}

// ---------------------------------------------------------------------------
// Inputs per metadata order:
// 0: ehr_vector (128*256)  1: criteria (32*64*256)  2: ec_mask (unused)
// 3: W_align (512)         4: b_align (unused, cancels in softmax)
// 5: W_mlp (512*256)       6: b_mlp (256)
// ---------------------------------------------------------------------------
extern "C" void kernel_launch(void* const* d_in, const int* in_sizes, int n_in,
                              void* d_out, int out_size) {
    const float* ehr     = (const float*)d_in[0];
    const float* crit    = (const float*)d_in[1];
    const float* W_align = (const float*)d_in[3];
    const float* W_mlp   = (const float*)d_in[5];
    const float* b_mlp   = (const float*)d_in[6];
    float* out = (float*)d_out;

    k_pre<<<ATT_BLOCKS + PE_BLOCKS, 256>>>(ehr, crit, W_align, W_mlp);

    // k_main with PDL: starts immediately, runs its GEMM phase on inputs
    // while k_pre computes att/PE, then pdl_wait gates the store phase.
    cudaLaunchConfig_t cfg = {};
    cfg.gridDim  = dim3(MAIN_BLOCKS, 1, 1);
    cfg.blockDim = dim3(512, 1, 1);
    cudaLaunchAttribute attrs[1];
    attrs[0].id = cudaLaunchAttributeProgrammaticStreamSerialization;
    attrs[0].val.programmaticStreamSerializationAllowed = 1;
    cfg.attrs = attrs;
    cfg.numAttrs = 1;
    cudaLaunchKernelEx(&cfg, k_main, out, crit, W_mlp, (const float*)b_mlp);
}

// round 12
// speedup vs baseline: 1.2909x; 1.2909x over previous
#include <cuda_runtime.h>
#include <cuda_bf16.h>

// Problem constants
#define BS1 32
#define BS2 128
#define NUM_EC 64
#define MEM_DIM 256
#define MLP_DIM 256
#define Q_DIM 256           // 4 * CONV_DIM

// Scratch (device globals — allocation is forbidden)
__device__ float g_att[BS1 * NUM_EC];              // softmax_e(criteria·Wa_c)
__device__ float g_PC [BS1 * NUM_EC * MLP_DIM];    // raw criteria @ Wm_c
__device__ float g_PE [BS2 * MLP_DIM];             // ehr @ Wm_e

// ---- PDL primitives ----
__device__ __forceinline__ void pdl_trigger() {
    asm volatile("griddepcontrol.launch_dependents;");
}
__device__ __forceinline__ void pdl_wait() {
    asm volatile("griddepcontrol.wait;" ::: "memory");
}

// ---- packed f32x2 helpers ----
__device__ __forceinline__ unsigned long long pk2(float lo, float hi) {
    unsigned long long r;
    asm("mov.b64 %0, {%1, %2};" : "=l"(r)
        : "r"(__float_as_uint(lo)), "r"(__float_as_uint(hi)));
    return r;
}
__device__ __forceinline__ unsigned long long fma2(unsigned long long a,
                                                   unsigned long long b,
                                                   unsigned long long c) {
    unsigned long long d;
    asm("fma.rn.f32x2 %0, %1, %2, %3;" : "=l"(d) : "l"(a), "l"(b), "l"(c));
    return d;
}
__device__ __forceinline__ float2 upk2(unsigned long long v) {
    unsigned int lo, hi;
    asm("mov.b64 {%0, %1}, %2;" : "=r"(lo), "=r"(hi) : "l"(v));
    return make_float2(__uint_as_float(lo), __uint_as_float(hi));
}

// ---------------------------------------------------------------------------
// Prep kernel, 320 blocks (R10 config + deeper W-LDG unroll):
//   bids [0,256):   PC[b,e,d] = dot(criteria[b,e,:], Wm_c[:,d])
//     Block = (b, e-tile of 16, d-half of 128); thread = (4d, 4e, k-half).
//     FMA2 paired across d; W float4 rows give packs free.
//   bids [256,288): att[b,:] = softmax_e(criteria[b,e,:]·Wa_c)
//   bids [288,320): PE[p,d] = dot(ehr[p,:], Wm_e[:,d])   (4 p / block)
// ---------------------------------------------------------------------------
#define C1_BLOCKS   256
#define ATT_BLOCKS  32
#define PE_BLOCKS   32
#define E_TILE      16
#define PE_P_TILE   4

__global__ void __launch_bounds__(256) k_prep(const float* __restrict__ ehr,
                                              const float* __restrict__ crit,
                                              const float* __restrict__ W_align,
                                              const float* __restrict__ W_mlp) {
    __shared__ __align__(16) float sbuf[E_TILE * Q_DIM];   // 16 KB, reused
    const int bid = blockIdx.x;
    const int tid = threadIdx.x;

    if (bid < C1_BLOCKS) {
        // ----- PC -----
        const int b   = bid >> 3;
        const int et  = (bid >> 1) & 3;
        const int dh  = bid & 1;
        const int e0  = et * E_TILE;
        const int dg  = tid & 31;          // d-group (4 d each)
        const int es  = (tid >> 5) & 3;    // e-subtile (4 e each)
        const int kh  = tid >> 7;          // k-half (0/1)
        const int dloc = dg * 4;           // d within the 128-wide half
        const int d0  = dh * 128 + dloc;   // global d

        // load criteria[b, e0..e0+15, 0..255]  (1024 float4, 4 per thread)
        float4* cs = (float4*)sbuf;        // [E_TILE][64]
        const float4* src = (const float4*)(crit + (size_t)(b * NUM_EC + e0) * Q_DIM);
        #pragma unroll
        for (int i = 0; i < 4; ++i)
            cs[tid + i * 256] = src[tid + i * 256];
        __syncthreads();

        // acc[4 e][4 d] as f32x2 pairs: (d0,d0+1) and (d0+2,d0+3)
        unsigned long long acc01[4], acc23[4];
        #pragma unroll
        for (int e = 0; e < 4; ++e) { acc01[e] = 0ull; acc23[e] = 0ull; }

        const int k4base = kh * 32;
        #pragma unroll 4
        for (int j = 0; j < 32; ++j) {
            const int k4 = k4base + j;
            const int k  = k4 * 4;
            const float4 w0 = *(const float4*)(W_mlp + (size_t)(k + 0) * MLP_DIM + d0);
            const float4 w1 = *(const float4*)(W_mlp + (size_t)(k + 1) * MLP_DIM + d0);
            const float4 w2 = *(const float4*)(W_mlp + (size_t)(k + 2) * MLP_DIM + d0);
            const float4 w3 = *(const float4*)(W_mlp + (size_t)(k + 3) * MLP_DIM + d0);
            const unsigned long long w0a = pk2(w0.x, w0.y), w0b = pk2(w0.z, w0.w);
            const unsigned long long w1a = pk2(w1.x, w1.y), w1b = pk2(w1.z, w1.w);
            const unsigned long long w2a = pk2(w2.x, w2.y), w2b = pk2(w2.z, w2.w);
            const unsigned long long w3a = pk2(w3.x, w3.y), w3b = pk2(w3.z, w3.w);
            #pragma unroll
            for (int e = 0; e < 4; ++e) {
                const float4 c = cs[(es * 4 + e) * 64 + k4];  // broadcast LDS.128
                unsigned long long cx = pk2(c.x, c.x);
                unsigned long long cy = pk2(c.y, c.y);
                unsigned long long cz = pk2(c.z, c.z);
                unsigned long long cw = pk2(c.w, c.w);
                acc01[e] = fma2(cx, w0a, acc01[e]);
                acc23[e] = fma2(cx, w0b, acc23[e]);
                acc01[e] = fma2(cy, w1a, acc01[e]);
                acc23[e] = fma2(cy, w1b, acc23[e]);
                acc01[e] = fma2(cz, w2a, acc01[e]);
                acc23[e] = fma2(cz, w2b, acc23[e]);
                acc01[e] = fma2(cw, w3a, acc01[e]);
                acc23[e] = fma2(cw, w3b, acc23[e]);
            }
        }
        __syncthreads();                   // criteria consumed; reuse as partials

        // partials: [2 kh][16 e][128 dloc]  = 16 KB
        float* part = sbuf;
        #pragma unroll
        for (int e = 0; e < 4; ++e) {
            const float2 a = upk2(acc01[e]);
            const float2 b2 = upk2(acc23[e]);
            float* p = part + ((kh * E_TILE + es * 4 + e) * 128 + dloc);
            p[0] = a.x; p[1] = a.y; p[2] = b2.x; p[3] = b2.y;
        }
        __syncthreads();

        // 2048 outputs, 256 threads -> 8 each (coalesced over dd)
        #pragma unroll
        for (int i = 0; i < 8; ++i) {
            const int idx = tid + i * 256;         // e*128 + dd
            const int e  = idx >> 7;
            const int dd = idx & 127;
            float v = part[e * 128 + dd] + part[(E_TILE + e) * 128 + dd];
            g_PC[((size_t)(b * NUM_EC + e0 + e)) * MLP_DIM + dh * 128 + dd] = v;
        }
        pdl_trigger();

    } else if (bid < C1_BLOCKS + ATT_BLOCKS) {
        // ----- att -----
        const int b = bid - C1_BLOCKS;
        const int e = tid >> 2;
        const int q = tid & 3;

        const float4* row = (const float4*)(crit + ((size_t)(b * NUM_EC + e)) * Q_DIM);
        const float4* wa  = (const float4*)W_align;

        float s = 0.f;
        #pragma unroll
        for (int i = 0; i < 16; ++i) {
            float4 c = row[q * 16 + i];
            float4 w = wa [q * 16 + i];
            s += c.x * w.x + c.y * w.y + c.z * w.z + c.w * w.w;
        }
        s += __shfl_xor_sync(0xffffffffu, s, 1);
        s += __shfl_xor_sync(0xffffffffu, s, 2);

        float* sm = sbuf;
        if (q == 0) sm[e] = s;
        __syncthreads();

        if (tid < 32) {
            float a  = sm[tid];
            float bb = sm[tid + 32];
            float m = fmaxf(a, bb);
            #pragma unroll
            for (int off = 16; off; off >>= 1)
                m = fmaxf(m, __shfl_xor_sync(0xffffffffu, m, off));
            float ea = expf(a - m);
            float eb = expf(bb - m);
            float ss = ea + eb;
            #pragma unroll
            for (int off = 16; off; off >>= 1)
                ss += __shfl_xor_sync(0xffffffffu, ss, off);
            float inv = 1.f / ss;
            g_att[b * NUM_EC + tid]      = ea * inv;
            g_att[b * NUM_EC + tid + 32] = eb * inv;
        }
        __syncthreads();
        pdl_trigger();

    } else {
        // ----- PE -----
        const int pg = bid - (C1_BLOCKS + ATT_BLOCKS);
        const int p0 = pg * PE_P_TILE;
        const int d  = tid;

        float* es = sbuf;                  // [PE_P_TILE][MEM_DIM]
        #pragma unroll
        for (int i = 0; i < PE_P_TILE; ++i)
            es[i * MEM_DIM + d] = ehr[(size_t)(p0 + i) * MEM_DIM + d];
        __syncthreads();

        float acc[PE_P_TILE];
        #pragma unroll
        for (int i = 0; i < PE_P_TILE; ++i) acc[i] = 0.f;

        const float* w = W_mlp + (size_t)Q_DIM * MLP_DIM + d;
        #pragma unroll 4
        for (int k = 0; k < MEM_DIM; ++k) {
            float wv = w[(size_t)k * MLP_DIM];
            #pragma unroll
            for (int i = 0; i < PE_P_TILE; ++i)
                acc[i] += es[i * MEM_DIM + k] * wv;
        }
        #pragma unroll
        for (int i = 0; i < PE_P_TILE; ++i)
            g_PE[(size_t)(p0 + i) * MLP_DIM + d] = acc[i];
        pdl_trigger();
    }
}

// ---------------------------------------------------------------------------
// Main (store-bound): out[b,p,e,d] = att[b,e]*(PC[b,e,d]+PE[p,d]) + b_mlp[d]
// NEW: P_TILE=2, grid = 32 b x 64 p-groups = 2048 blocks, block = 256.
// More blocks = more concurrent store streams; each block still sweeps two
// fully contiguous 64 KB output rows (locality preserved). PDL wait before
// touching prep outputs.
// ---------------------------------------------------------------------------
#define P_TILE 2
__global__ void __launch_bounds__(256) k_main(float* __restrict__ out,
                                              const float* __restrict__ b_mlp) {
    const int b   = blockIdx.x >> 6;
    const int pg  = blockIdx.x & 63;
    const int p0  = pg * P_TILE;
    const int tid = threadIdx.x;
    const int v   = tid & 63;

    // Prologue on inputs only (safe before the dependency resolves)
    const float4 bm = __ldg((const float4*)b_mlp + v);
    float4* o = (float4*)out;
    const size_t base = (size_t)b * (BS2 * NUM_EC * (MLP_DIM / 4))
                      + (size_t)p0 * (NUM_EC * (MLP_DIM / 4));
    const int stride_p = NUM_EC * (MLP_DIM / 4);    // 4096 float4

    pdl_wait();

    __shared__ float atts[NUM_EC];
    if (tid < NUM_EC) atts[tid] = g_att[b * NUM_EC + tid];
    __syncthreads();

    const float4 pe0 = __ldg((const float4*)g_PE + (size_t)(p0 + 0) * (MLP_DIM / 4) + v);
    const float4 pe1 = __ldg((const float4*)g_PE + (size_t)(p0 + 1) * (MLP_DIM / 4) + v);

    const float4* pc = (const float4*)g_PC + (size_t)b * NUM_EC * (MLP_DIM / 4);

    #pragma unroll 4
    for (int k = 0; k < 16; ++k) {
        const int i = tid + k * 256;
        const float  a = atts[i >> 6];
        const float4 c = __ldg(&pc[i]);
        float4 r0, r1;
        r0.x = fmaf(a, c.x + pe0.x, bm.x); r0.y = fmaf(a, c.y + pe0.y, bm.y);
        r0.z = fmaf(a, c.z + pe0.z, bm.z); r0.w = fmaf(a, c.w + pe0.w, bm.w);
        r1.x = fmaf(a, c.x + pe1.x, bm.x); r1.y = fmaf(a, c.y + pe1.y, bm.y);
        r1.z = fmaf(a, c.z + pe1.z, bm.z); r1.w = fmaf(a, c.w + pe1.w, bm.w);
        __stcs(&o[base + 0 * stride_p + i], r0);
        __stcs(&o[base + 1 * stride_p + i], r1);
    }
}

// ---------------------------------------------------------------------------
// Inputs per metadata order:
// 0: ehr_vector (128*256)  1: criteria (32*64*256)  2: ec_mask (unused)
// 3: W_align (512)         4: b_align (unused, cancels in softmax)
// 5: W_mlp (512*256)       6: b_mlp (256)
// ---------------------------------------------------------------------------
extern "C" void kernel_launch(void* const* d_in, const int* in_sizes, int n_in,
                              void* d_out, int out_size) {
    const float* ehr     = (const float*)d_in[0];
    const float* crit    = (const float*)d_in[1];
    const float* W_align = (const float*)d_in[3];
    const float* W_mlp   = (const float*)d_in[5];
    const float* b_mlp   = (const float*)d_in[6];
    float* out = (float*)d_out;

    k_prep<<<C1_BLOCKS + ATT_BLOCKS + PE_BLOCKS, 256>>>(ehr, crit, W_align, W_mlp);

    cudaLaunchConfig_t cfg = {};
    cfg.gridDim  = dim3(BS1 * (BS2 / P_TILE), 1, 1);
    cfg.blockDim = dim3(256, 1, 1);
    cudaLaunchAttribute attrs[1];
    attrs[0].id = cudaLaunchAttributeProgrammaticStreamSerialization;
    attrs[0].val.programmaticStreamSerializationAllowed = 1;
    cfg.attrs = attrs;
    cfg.numAttrs = 1;
    cudaLaunchKernelEx(&cfg, k_main, out, (const float*)b_mlp);
}